// round 17
// baseline (speedup 1.0000x reference)
#include <cuda_runtime.h>
#include <cuda_bf16.h>
#include <cstdint>
#include <math.h>

#define D_MODEL 2048
#define SEQ     2048
#define BATCH   2
#define NHEADS  16
#define DK      128
#define MROWS   (BATCH*SEQ)   /* 4096 */

// ---------------- scratch ----------------
__device__ float g_cos[SEQ * (DK / 2)];
__device__ float g_sin[SEQ * (DK / 2)];

__device__ __nv_bfloat16 g_xh[(size_t)MROWS * D_MODEL];
__device__ __nv_bfloat16 g_xl[(size_t)MROWS * D_MODEL];
__device__ __nv_bfloat16 g_wqh[(size_t)D_MODEL * D_MODEL];
__device__ __nv_bfloat16 g_wql[(size_t)D_MODEL * D_MODEL];
__device__ __nv_bfloat16 g_wkh[(size_t)D_MODEL * D_MODEL];
__device__ __nv_bfloat16 g_wkl[(size_t)D_MODEL * D_MODEL];
__device__ __nv_bfloat16 g_wvh[(size_t)D_MODEL * D_MODEL];
__device__ __nv_bfloat16 g_wvl[(size_t)D_MODEL * D_MODEL];
__device__ __nv_bfloat16 g_woh[(size_t)D_MODEL * D_MODEL];
__device__ __nv_bfloat16 g_wol[(size_t)D_MODEL * D_MODEL];
__device__ __nv_bfloat16 g_ah[(size_t)MROWS * D_MODEL];
__device__ __nv_bfloat16 g_al[(size_t)MROWS * D_MODEL];

__device__ __nv_bfloat16 g_qh[(size_t)MROWS * D_MODEL];
__device__ __nv_bfloat16 g_ql[(size_t)MROWS * D_MODEL];
__device__ __nv_bfloat16 g_kh[(size_t)MROWS * D_MODEL];
__device__ __nv_bfloat16 g_kl[(size_t)MROWS * D_MODEL];
__device__ __nv_bfloat16 g_vh[(size_t)MROWS * D_MODEL];
__device__ __nv_bfloat16 g_vl[(size_t)MROWS * D_MODEL];

// ---------------- PTX helpers ----------------
__device__ __forceinline__ void cpa16(uint32_t dst, const void* src) {
    asm volatile("cp.async.cg.shared.global [%0], [%1], 16;" :: "r"(dst), "l"(src));
}
#define CPA_COMMIT() asm volatile("cp.async.commit_group;" ::: "memory")
#define CPA_WAIT0()  asm volatile("cp.async.wait_group 0;" ::: "memory")
#define CPA_WAIT1()  asm volatile("cp.async.wait_group 1;" ::: "memory")

__device__ __forceinline__ uint32_t su32(const void* p) {
    uint32_t a;
    asm("{ .reg .u64 t; cvta.to.shared.u64 t, %1; cvt.u32.u64 %0, t; }" : "=r"(a) : "l"(p));
    return a;
}

#define LDSM4(r0, r1, r2, r3, a) \
    asm volatile("ldmatrix.sync.aligned.m8n8.x4.shared.b16 {%0,%1,%2,%3}, [%4];" \
                 : "=r"(r0), "=r"(r1), "=r"(r2), "=r"(r3) : "r"(a))
#define LDSM4T(r0, r1, r2, r3, a) \
    asm volatile("ldmatrix.sync.aligned.m8n8.x4.trans.shared.b16 {%0,%1,%2,%3}, [%4];" \
                 : "=r"(r0), "=r"(r1), "=r"(r2), "=r"(r3) : "r"(a))
#define MMA16816(d, a0, a1, a2, a3, b0, b1) \
    asm volatile("mma.sync.aligned.m16n8k16.row.col.f32.bf16.bf16.f32 " \
                 "{%0,%1,%2,%3}, {%4,%5,%6,%7}, {%8,%9}, {%0,%1,%2,%3};" \
                 : "+f"((d)[0]), "+f"((d)[1]), "+f"((d)[2]), "+f"((d)[3]) \
                 : "r"(a0), "r"(a1), "r"(a2), "r"(a3), "r"(b0), "r"(b1))

__device__ __forceinline__ uint32_t packbf(float lo, float hi) {
    uint32_t u;
    asm("cvt.rn.bf16x2.f32 %0, %1, %2;" : "=r"(u) : "f"(hi), "f"(lo));
    return u;
}
__device__ __forceinline__ float bfres(float x) {
    return x - __bfloat162float(__float2bfloat16(x));
}

// fast exp2 on FMA pipe (arg <= 0)
__device__ __forceinline__ float exp2ff(float x) {
    x = fmaxf(x, -126.0f);
    float fl = floorf(x);
    float f = x - fl;
    float p = 1.54035304e-4f;
    p = fmaf(p, f, 1.33335581e-3f);
    p = fmaf(p, f, 9.61812910e-3f);
    p = fmaf(p, f, 5.55041086e-2f);
    p = fmaf(p, f, 2.40226512e-1f);
    p = fmaf(p, f, 6.93147182e-1f);
    p = fmaf(p, f, 1.0f);
    return __uint_as_float((uint32_t)((int)fl + 127) << 23) * p;
}

// ---------------- split helper ----------------
__device__ __forceinline__ void split4(const float* __restrict__ src,
                                       __nv_bfloat16* __restrict__ hi,
                                       __nv_bfloat16* __restrict__ lo, int i) {
    float4 v = ((const float4*)src)[i];
    __nv_bfloat16 h0 = __float2bfloat16(v.x);
    __nv_bfloat16 h1 = __float2bfloat16(v.y);
    __nv_bfloat16 h2 = __float2bfloat16(v.z);
    __nv_bfloat16 h3 = __float2bfloat16(v.w);
    __nv_bfloat16 l0 = __float2bfloat16(v.x - __bfloat162float(h0));
    __nv_bfloat16 l1 = __float2bfloat16(v.y - __bfloat162float(h1));
    __nv_bfloat16 l2 = __float2bfloat16(v.z - __bfloat162float(h2));
    __nv_bfloat16 l3 = __float2bfloat16(v.w - __bfloat162float(h3));
    uint2 hp, lp;
    hp.x = (uint32_t)__bfloat16_as_ushort(h0) | ((uint32_t)__bfloat16_as_ushort(h1) << 16);
    hp.y = (uint32_t)__bfloat16_as_ushort(h2) | ((uint32_t)__bfloat16_as_ushort(h3) << 16);
    lp.x = (uint32_t)__bfloat16_as_ushort(l0) | ((uint32_t)__bfloat16_as_ushort(l1) << 16);
    lp.y = (uint32_t)__bfloat16_as_ushort(l2) | ((uint32_t)__bfloat16_as_ushort(l3) << 16);
    ((uint2*)hi)[i] = hp;
    ((uint2*)lo)[i] = lp;
}

// ---------------- fused prep: rope tables + input/weight splits --------------
__global__ void prep_kernel(const float* __restrict__ x,
                            const float* __restrict__ Wq, const float* __restrict__ Wk,
                            const float* __restrict__ Wv, const float* __restrict__ Wo) {
    int bid = blockIdx.x;
    int t = threadIdx.x;
    if (bid < 512) {
        int idx = bid * 256 + t;
        int s = idx >> 6;
        int i = idx & 63;
        float th = powf(10000.0f, (float)i * (1.0f / 64.0f));
        float ph = (float)s / th;          // fp32 rounding matches reference
        double phd = (double)ph;
        g_cos[idx] = (float)cos(phd);
        g_sin[idx] = (float)sin(phd);
    } else if (bid < 8704) {
        split4(x, g_xh, g_xl, (bid - 512) * 256 + t);
    } else {
        int r = bid - 8704;
        int which = r >> 12;
        int i = (r & 4095) * 256 + t;
        if (which == 0)      split4(Wq, g_wqh, g_wql, i);
        else if (which == 1) split4(Wk, g_wkh, g_wkl, i);
        else if (which == 2) split4(Wv, g_wvh, g_wvl, i);
        else                 split4(Wo, g_woh, g_wol, i);
    }
}

// ============================================================================
// bf16 GEMM core: C[M,N] = A[M,K]*B[N,K]^T, 3-term split precision.
// CTA 128x128, 8 warps (64x32 each), Kc=32, 3-stage cp.async, XOR swizzle.
// A-fragment double buffering: LDSM for mi+1 issued before MMAs of mi.
// mode 0: fp32 C; mode 1: bf16 hi/lo; mode 2: RoPE then bf16 hi/lo.
// ============================================================================
#define GKC    32
#define GMAT   8192                 /* 128 rows x 64B per matrix */
#define GSTG   (4 * GMAT)           /* 32768 per stage */
#define SMEM_G (3 * GSTG)           /* 98304 */

__device__ __forceinline__ void g_load(
    uint32_t sdst, const __nv_bfloat16* __restrict__ Ah, const __nv_bfloat16* __restrict__ Al,
    const __nv_bfloat16* __restrict__ Bh, const __nv_bfloat16* __restrict__ Bl,
    int m0, int n0, int k0, int K, int tid) {
    const __nv_bfloat16* srcs[4] = {Ah, Al, Bh, Bl};
#pragma unroll
    for (int t = 0; t < 8; ++t) {
        int u = t * 256 + tid;            // 0..2047: 4 mats x 128 rows x 4 chunks
        int mtx = u >> 9;
        int rem = u & 511;
        int row = rem >> 2;
        int c16 = (rem & 3) << 4;
        int gr = (mtx < 2 ? m0 : n0) + row;
        cpa16(sdst + mtx * GMAT + row * 64 + (c16 ^ ((row & 6) << 3)),
              srcs[mtx] + (size_t)gr * K + k0 + (c16 >> 1));
    }
}

__device__ __forceinline__ void gemm_core(
    const __nv_bfloat16* __restrict__ Ah, const __nv_bfloat16* __restrict__ Al,
    const __nv_bfloat16* __restrict__ Bh, const __nv_bfloat16* __restrict__ Bl,
    float* __restrict__ C, __nv_bfloat16* __restrict__ Ch, __nv_bfloat16* __restrict__ Cl,
    int mode, int N, int K, char* smem) {
    const uint32_t sbase = su32(smem);
    const int tid  = threadIdx.x;
    const int wid  = tid >> 5;
    const int lane = tid & 31;
    const int m0 = blockIdx.y * 128;
    const int n0 = blockIdx.x * 128;
    const int wm = (wid & 1) * 64;        // 2x4 grid of 64x32 warp tiles
    const int wn = (wid >> 1) * 32;
    const int nchunk = K / GKC;           // 64

    float acc[4][4][4];
#pragma unroll
    for (int mi = 0; mi < 4; ++mi)
#pragma unroll
        for (int n8 = 0; n8 < 4; ++n8) {
            acc[mi][n8][0] = 0.f; acc[mi][n8][1] = 0.f;
            acc[mi][n8][2] = 0.f; acc[mi][n8][3] = 0.f;
        }

    g_load(sbase, Ah, Al, Bh, Bl, m0, n0, 0, K, tid);
    CPA_COMMIT();
    g_load(sbase + GSTG, Ah, Al, Bh, Bl, m0, n0, GKC, K, tid);
    CPA_COMMIT();

    const int r15 = lane & 15;
    const uint32_t xv = (uint32_t)((r15 & 6) << 3);
    const uint32_t chalf = (uint32_t)((lane >> 4) << 4);

#pragma unroll 1
    for (int c = 0; c < nchunk; ++c) {
        CPA_WAIT1();
        __syncthreads();
        if (c + 2 < nchunk) {
            g_load(sbase + ((c + 2) % 3) * GSTG, Ah, Al, Bh, Bl,
                   m0, n0, (c + 2) * GKC, K, tid);
            CPA_COMMIT();
        }
        const uint32_t sa = sbase + (c % 3) * GSTG;
#pragma unroll
        for (int ks = 0; ks < 2; ++ks) {
            const uint32_t cc = (uint32_t)(ks * 32) + chalf;
            uint32_t fb[2][4], fbl[2][4];
#pragma unroll
            for (int ni = 0; ni < 2; ++ni) {
                uint32_t row = (uint32_t)(wn + ni * 16 + r15);
                uint32_t bd = sa + 2 * GMAT + row * 64 + (cc ^ xv);
                LDSM4(fb[ni][0], fb[ni][1], fb[ni][2], fb[ni][3], bd);
                LDSM4(fbl[ni][0], fbl[ni][1], fbl[ni][2], fbl[ni][3], bd + GMAT);
            }
            // A frags double-buffered: prefetch mi+1 before MMAs of mi
            uint32_t fa[2][4], fal[2][4];
            {
                uint32_t row0 = (uint32_t)(wm + r15);
                uint32_t ad0 = sa + row0 * 64 + (cc ^ xv);
                LDSM4(fa[0][0], fa[0][1], fa[0][2], fa[0][3], ad0);
                LDSM4(fal[0][0], fal[0][1], fal[0][2], fal[0][3], ad0 + GMAT);
            }
#pragma unroll
            for (int mi = 0; mi < 4; ++mi) {
                const int cur = mi & 1;
                const int nxt = cur ^ 1;
                if (mi < 3) {
                    uint32_t row = (uint32_t)(wm + (mi + 1) * 16 + r15);
                    uint32_t ad = sa + row * 64 + (cc ^ xv);
                    LDSM4(fa[nxt][0], fa[nxt][1], fa[nxt][2], fa[nxt][3], ad);
                    LDSM4(fal[nxt][0], fal[nxt][1], fal[nxt][2], fal[nxt][3], ad + GMAT);
                }
                // term 1: Ah*Bh
#pragma unroll
                for (int n8 = 0; n8 < 4; ++n8)
                    MMA16816(acc[mi][n8], fa[cur][0], fa[cur][1], fa[cur][2], fa[cur][3],
                             fb[n8 >> 1][n8 & 1], fb[n8 >> 1][(n8 & 1) + 2]);
                // term 2: Ah*Bl
#pragma unroll
                for (int n8 = 0; n8 < 4; ++n8)
                    MMA16816(acc[mi][n8], fa[cur][0], fa[cur][1], fa[cur][2], fa[cur][3],
                             fbl[n8 >> 1][n8 & 1], fbl[n8 >> 1][(n8 & 1) + 2]);
                // term 3: Al*Bh
#pragma unroll
                for (int n8 = 0; n8 < 4; ++n8)
                    MMA16816(acc[mi][n8], fal[cur][0], fal[cur][1], fal[cur][2], fal[cur][3],
                             fb[n8 >> 1][n8 & 1], fb[n8 >> 1][(n8 & 1) + 2]);
            }
        }
    }

    // ---- epilogue ----
    const int group = lane >> 2;
    const int tig = lane & 3;
#pragma unroll
    for (int mi = 0; mi < 4; ++mi)
#pragma unroll
        for (int n8 = 0; n8 < 4; ++n8) {
            int grow = m0 + wm + mi * 16 + group;
            size_t row0 = (size_t)grow * N;
            size_t row1 = row0 + (size_t)8 * N;
            int col = n0 + wn + n8 * 8 + tig * 2;
            float d0 = acc[mi][n8][0], d1 = acc[mi][n8][1];
            float d2 = acc[mi][n8][2], d3 = acc[mi][n8][3];
            if (mode == 0) {
                *(float2*)(C + row0 + col) = make_float2(d0, d1);
                *(float2*)(C + row1 + col) = make_float2(d2, d3);
            } else {
                if (mode == 2) {   // RoPE on the interleaved pair
                    int i = ((wn + n8 * 8) >> 1) + tig;      // pair index in head
                    int s0 = grow & (SEQ - 1);
                    float c0 = g_cos[s0 * 64 + i], sn0 = g_sin[s0 * 64 + i];
                    float c1 = g_cos[(s0 + 8) * 64 + i], sn1 = g_sin[(s0 + 8) * 64 + i];
                    float t0 = d0 * c0 - d1 * sn0, t1 = d0 * sn0 + d1 * c0;
                    float t2 = d2 * c1 - d3 * sn1, t3 = d2 * sn1 + d3 * c1;
                    d0 = t0; d1 = t1; d2 = t2; d3 = t3;
                }
                __nv_bfloat16 h0 = __float2bfloat16(d0), h1 = __float2bfloat16(d1);
                __nv_bfloat16 h2 = __float2bfloat16(d2), h3 = __float2bfloat16(d3);
                *(__nv_bfloat162*)(Ch + row0 + col) = __halves2bfloat162(h0, h1);
                *(__nv_bfloat162*)(Ch + row1 + col) = __halves2bfloat162(h2, h3);
                *(__nv_bfloat162*)(Cl + row0 + col) = __halves2bfloat162(
                    __float2bfloat16(d0 - __bfloat162float(h0)),
                    __float2bfloat16(d1 - __bfloat162float(h1)));
                *(__nv_bfloat162*)(Cl + row1 + col) = __halves2bfloat162(
                    __float2bfloat16(d2 - __bfloat162float(h2)),
                    __float2bfloat16(d3 - __bfloat162float(h3)));
            }
        }
}

// fused Q/K/V projection: blockIdx.z selects weights/outputs/mode
__global__ void __launch_bounds__(256, 2) gemm_qkv() {
    extern __shared__ char smem[];
    const int z = blockIdx.z;
    const __nv_bfloat16* Bh = (z == 0) ? g_wqh : (z == 1) ? g_wkh : g_wvh;
    const __nv_bfloat16* Bl = (z == 0) ? g_wql : (z == 1) ? g_wkl : g_wvl;
    __nv_bfloat16* Ch = (z == 0) ? g_qh : (z == 1) ? g_kh : g_vh;
    __nv_bfloat16* Cl = (z == 0) ? g_ql : (z == 1) ? g_kl : g_vl;
    const int mode = (z < 2) ? 2 : 1;
    gemm_core(g_xh, g_xl, Bh, Bl, nullptr, Ch, Cl, mode, D_MODEL, D_MODEL, smem);
}

// out projection
__global__ void __launch_bounds__(256, 2) gemm_out(float* __restrict__ C) {
    extern __shared__ char smem[];
    gemm_core(g_ah, g_al, g_woh, g_wol, C, nullptr, nullptr, 0,
              D_MODEL, D_MODEL, smem);
}

// ============================================================================
// Flash attention (unchanged; epilogue writes ah/al bf16 hi/lo)
// ============================================================================
#define FPITCH 272
#define FKT    (64 * FPITCH)
#define QOFF   0
#define KOFF   (2 * FKT)
#define VOFF   (4 * FKT)
#define SMEM_FLASH (6 * FKT)       /* 104448 */

__device__ __forceinline__ void ld_pair(uint32_t sdst, const __nv_bfloat16* __restrict__ h,
                                        const __nv_bfloat16* __restrict__ l,
                                        int brow0, int hcol, int tid) {
#pragma unroll
    for (int t = 0; t < 16; ++t) {
        int u = t * 128 + tid;
        int mtx = u >> 10;
        int rem = u & 1023;
        int row = rem >> 4;
        int c16 = rem & 15;
        const __nv_bfloat16* src = mtx ? l : h;
        cpa16(sdst + mtx * FKT + row * FPITCH + c16 * 16,
              src + (size_t)(brow0 + row) * D_MODEL + hcol + c16 * 8);
    }
}

__global__ void __launch_bounds__(128) flash_tc() {
    extern __shared__ char smem[];
    const uint32_t sbase = su32(smem);
    const int tid  = threadIdx.x;
    const int wid  = tid >> 5;
    const int lane = tid & 31;
    const int qb   = (int)gridDim.x - 1 - (int)blockIdx.x;
    const int h    = blockIdx.y;
    const int b    = blockIdx.z;
    const int hcol = h * DK;
    const int brow0q = b * SEQ + qb * 64;
    const int group = lane >> 2;
    const int tig   = lane & 3;
    const int qg0   = qb * 64 + wid * 16 + group;

    const float SCL2 = 0.08838834764831845f * 1.4426950408889634f;

    ld_pair(sbase + QOFF, g_qh, g_ql, brow0q, hcol, tid);
    ld_pair(sbase + KOFF, g_kh, g_kl, b * SEQ, hcol, tid);
    CPA_COMMIT();
    ld_pair(sbase + VOFF, g_vh, g_vl, b * SEQ, hcol, tid);
    CPA_COMMIT();

    float oacc[16][4];
#pragma unroll
    for (int f = 0; f < 16; ++f) {
        oacc[f][0] = 0.f; oacc[f][1] = 0.f; oacc[f][2] = 0.f; oacc[f][3] = 0.f;
    }
    float m2[2] = {-1e30f, -1e30f};
    float lsum[2] = {0.f, 0.f};

    const int nt = qb + 1;
    const uint32_t qrow_base = sbase + QOFF + (wid * 16 + (lane & 15)) * FPITCH
                             + (lane >> 4) * 16;
    const uint32_t krow = sbase + KOFF + (lane & 15) * FPITCH + (lane >> 4) * 16;
    const uint32_t vrow = sbase + VOFF
                        + ((lane & 7) + ((lane >> 3) & 1) * 8) * FPITCH
                        + ((lane >> 4) & 1) * 16;

    for (int t = 0; t < nt; ++t) {
        CPA_WAIT1();
        __syncthreads();

        float sacc[8][4];
#pragma unroll
        for (int f = 0; f < 8; ++f) {
            sacc[f][0] = 0.f; sacc[f][1] = 0.f; sacc[f][2] = 0.f; sacc[f][3] = 0.f;
        }
#pragma unroll
        for (int kc = 0; kc < 8; ++kc) {
            uint32_t qa0, qa1, qa2, qa3, ql0, ql1, ql2, ql3;
            LDSM4(qa0, qa1, qa2, qa3, qrow_base + kc * 32);
            LDSM4(ql0, ql1, ql2, ql3, qrow_base + FKT + kc * 32);
#pragma unroll
            for (int nf2 = 0; nf2 < 4; ++nf2) {
                uint32_t kh0, kh1, kh2, kh3, kl0, kl1, kl2, kl3;
                uint32_t ka = krow + nf2 * (16 * FPITCH) + kc * 32;
                LDSM4(kh0, kh1, kh2, kh3, ka);
                LDSM4(kl0, kl1, kl2, kl3, ka + FKT);
                MMA16816(sacc[2 * nf2],     qa0, qa1, qa2, qa3, kh0, kh2);
                MMA16816(sacc[2 * nf2 + 1], qa0, qa1, qa2, qa3, kh1, kh3);
                MMA16816(sacc[2 * nf2],     qa0, qa1, qa2, qa3, kl0, kl2);
                MMA16816(sacc[2 * nf2 + 1], qa0, qa1, qa2, qa3, kl1, kl3);
                MMA16816(sacc[2 * nf2],     ql0, ql1, ql2, ql3, kh0, kh2);
                MMA16816(sacc[2 * nf2 + 1], ql0, ql1, ql2, ql3, kh1, kh3);
            }
        }
        __syncthreads();
        if (t + 1 < nt) {
            ld_pair(sbase + KOFF, g_kh, g_kl, b * SEQ + (t + 1) * 64, hcol, tid);
            CPA_COMMIT();
        }

        if (t == qb) {
            const int j0 = t * 64;
#pragma unroll
            for (int f = 0; f < 8; ++f) {
                int col = j0 + f * 8 + tig * 2;
                if (col > qg0)          sacc[f][0] = -1e30f;
                if (col + 1 > qg0)      sacc[f][1] = -1e30f;
                if (col > qg0 + 8)      sacc[f][2] = -1e30f;
                if (col + 1 > qg0 + 8)  sacc[f][3] = -1e30f;
            }
        }

        float mn0 = -1e30f, mn1 = -1e30f;
#pragma unroll
        for (int f = 0; f < 8; ++f) {
            mn0 = fmaxf(mn0, fmaxf(sacc[f][0], sacc[f][1]));
            mn1 = fmaxf(mn1, fmaxf(sacc[f][2], sacc[f][3]));
        }
        mn0 = fmaxf(mn0, __shfl_xor_sync(0xffffffffu, mn0, 1));
        mn0 = fmaxf(mn0, __shfl_xor_sync(0xffffffffu, mn0, 2));
        mn1 = fmaxf(mn1, __shfl_xor_sync(0xffffffffu, mn1, 1));
        mn1 = fmaxf(mn1, __shfl_xor_sync(0xffffffffu, mn1, 2));
        float mN0 = fmaxf(m2[0], mn0), mN1 = fmaxf(m2[1], mn1);
        float corr0 = exp2ff(SCL2 * (m2[0] - mN0));
        float corr1 = exp2ff(SCL2 * (m2[1] - mN1));
        m2[0] = mN0; m2[1] = mN1;
        const float b0 = mN0 * SCL2, b1 = mN1 * SCL2;

        float ls0 = 0.f, ls1 = 0.f;
#pragma unroll
        for (int f = 0; f < 8; ++f) {
            sacc[f][0] = exp2ff(fmaf(sacc[f][0], SCL2, -b0));
            sacc[f][1] = exp2ff(fmaf(sacc[f][1], SCL2, -b0));
            sacc[f][2] = exp2ff(fmaf(sacc[f][2], SCL2, -b1));
            sacc[f][3] = exp2ff(fmaf(sacc[f][3], SCL2, -b1));
            ls0 += sacc[f][0] + sacc[f][1];
            ls1 += sacc[f][2] + sacc[f][3];
        }
        ls0 += __shfl_xor_sync(0xffffffffu, ls0, 1);
        ls0 += __shfl_xor_sync(0xffffffffu, ls0, 2);
        ls1 += __shfl_xor_sync(0xffffffffu, ls1, 1);
        ls1 += __shfl_xor_sync(0xffffffffu, ls1, 2);
        lsum[0] = lsum[0] * corr0 + ls0;
        lsum[1] = lsum[1] * corr1 + ls1;

#pragma unroll
        for (int f = 0; f < 16; ++f) {
            oacc[f][0] *= corr0; oacc[f][1] *= corr0;
            oacc[f][2] *= corr1; oacc[f][3] *= corr1;
        }

        if (t + 1 < nt) CPA_WAIT1(); else CPA_WAIT0();
        __syncthreads();

#pragma unroll
        for (int kc = 0; kc < 4; ++kc) {
            const int f0 = 2 * kc, f1 = 2 * kc + 1;
            uint32_t ph0 = packbf(sacc[f0][0], sacc[f0][1]);
            uint32_t ph1 = packbf(sacc[f0][2], sacc[f0][3]);
            uint32_t ph2 = packbf(sacc[f1][0], sacc[f1][1]);
            uint32_t ph3 = packbf(sacc[f1][2], sacc[f1][3]);
            uint32_t pl0 = packbf(bfres(sacc[f0][0]), bfres(sacc[f0][1]));
            uint32_t pl1 = packbf(bfres(sacc[f0][2]), bfres(sacc[f0][3]));
            uint32_t pl2 = packbf(bfres(sacc[f1][0]), bfres(sacc[f1][1]));
            uint32_t pl3 = packbf(bfres(sacc[f1][2]), bfres(sacc[f1][3]));
#pragma unroll
            for (int nf2 = 0; nf2 < 8; ++nf2) {
                uint32_t va = vrow + kc * (16 * FPITCH) + nf2 * 32;
                uint32_t v0, v1, v2, v3, u0, u1, u2, u3;
                LDSM4T(v0, v1, v2, v3, va);
                LDSM4T(u0, u1, u2, u3, va + FKT);
                MMA16816(oacc[2 * nf2],     ph0, ph1, ph2, ph3, v0, v1);
                MMA16816(oacc[2 * nf2 + 1], ph0, ph1, ph2, ph3, v2, v3);
                MMA16816(oacc[2 * nf2],     ph0, ph1, ph2, ph3, u0, u1);
                MMA16816(oacc[2 * nf2 + 1], ph0, ph1, ph2, ph3, u2, u3);
                MMA16816(oacc[2 * nf2],     pl0, pl1, pl2, pl3, v0, v1);
                MMA16816(oacc[2 * nf2 + 1], pl0, pl1, pl2, pl3, v2, v3);
            }
        }
        __syncthreads();
        if (t + 1 < nt) {
            ld_pair(sbase + VOFF, g_vh, g_vl, b * SEQ + (t + 1) * 64, hcol, tid);
            CPA_COMMIT();
        }
    }

    const float inv0 = 1.0f / lsum[0];
    const float inv1 = 1.0f / lsum[1];
    size_t r0 = (size_t)(brow0q + wid * 16 + group) * D_MODEL + hcol;
    size_t r1 = r0 + (size_t)8 * D_MODEL;
#pragma unroll
    for (int f = 0; f < 16; ++f) {
        const int col = f * 8 + tig * 2;
        float o0 = oacc[f][0] * inv0, o1 = oacc[f][1] * inv0;
        float o2 = oacc[f][2] * inv1, o3 = oacc[f][3] * inv1;
        __nv_bfloat16 h0 = __float2bfloat16(o0), h1 = __float2bfloat16(o1);
        __nv_bfloat16 h2 = __float2bfloat16(o2), h3 = __float2bfloat16(o3);
        *(__nv_bfloat162*)(g_ah + r0 + col) = __halves2bfloat162(h0, h1);
        *(__nv_bfloat162*)(g_ah + r1 + col) = __halves2bfloat162(h2, h3);
        *(__nv_bfloat162*)(g_al + r0 + col) = __halves2bfloat162(
            __float2bfloat16(o0 - __bfloat162float(h0)),
            __float2bfloat16(o1 - __bfloat162float(h1)));
        *(__nv_bfloat162*)(g_al + r1 + col) = __halves2bfloat162(
            __float2bfloat16(o2 - __bfloat162float(h2)),
            __float2bfloat16(o3 - __bfloat162float(h3)));
    }
}

// ---------------- launch ----------------
extern "C" void kernel_launch(void* const* d_in, const int* in_sizes, int n_in,
                              void* d_out, int out_size) {
    const float* x  = (const float*)d_in[0];
    const float* Wq = (const float*)d_in[2];
    const float* Wk = (const float*)d_in[3];
    const float* Wv = (const float*)d_in[4];
    const float* Wo = (const float*)d_in[5];
    float* out = (float*)d_out;

    cudaFuncSetAttribute(gemm_qkv, cudaFuncAttributeMaxDynamicSharedMemorySize, SMEM_G);
    cudaFuncSetAttribute(gemm_out, cudaFuncAttributeMaxDynamicSharedMemorySize, SMEM_G);
    cudaFuncSetAttribute(flash_tc, cudaFuncAttributeMaxDynamicSharedMemorySize, SMEM_FLASH);

    prep_kernel<<<8704 + 4 * 4096, 256>>>(x, Wq, Wk, Wv, Wo);                       // 0
    gemm_qkv<<<dim3(D_MODEL / 128, MROWS / 128, 3), 256, SMEM_G>>>();               // 1
    flash_tc<<<dim3(SEQ / 64, NHEADS, BATCH), 128, SMEM_FLASH>>>();                 // 2
    gemm_out<<<dim3(D_MODEL / 128, MROWS / 128), 256, SMEM_G>>>(out);               // 3
}